// round 16
// baseline (speedup 1.0000x reference)
#include <cuda_runtime.h>
#include <cuda_bf16.h>
#include <math.h>

#define TS 2048
#define NR 65536
typedef long long ll;
typedef unsigned int u32;
typedef unsigned long long ull;

// ------------------------- scratch (no allocations) -------------------------
__device__ float g_pref[(ll)NR*1024];
__device__ float g_preb[(ll)NR*1024];
__device__ float g_res [(ll)NR*512];
__device__ float g_h0  [(ll)NR*512];
__device__ float g_h1  [(ll)NR*512];
__device__ float g_hid [(ll)NR*128];
__device__ __nv_bfloat16 g_a3[(ll)NR*3072];        // split-bf16 A
__device__ __nv_bfloat16 g_b3[3][(ll)1024*3072];   // split-bf16 weights, 3 slots

// ---------------------- fp32 -> split bf16 conversions -----------------------
__global__ void k_cvtA(const float* __restrict__ A, __nv_bfloat16* __restrict__ A3,
                       int K, int flags)
{
    ll idx = (ll)blockIdx.x*256 + threadIdx.x;
    ll m = idx / (K>>2);
    int k4 = (int)(idx % (K>>2)) << 2;
    const float* src = (flags&1) ? A + ((m&31)*(ll)TS + (m>>5))*K + k4
                                 : A + m*(ll)K + k4;
    float4 v = *(const float4*)src;
    if (flags&1) {
        v.x=(v.x==v.x)?v.x:0.f; v.y=(v.y==v.y)?v.y:0.f;
        v.z=(v.z==v.z)?v.z:0.f; v.w=(v.w==v.w)?v.w:0.f;
    }
    __nv_bfloat16 h0=__float2bfloat16(v.x), h1=__float2bfloat16(v.y),
                  h2=__float2bfloat16(v.z), h3=__float2bfloat16(v.w);
    __nv_bfloat16 l0=__float2bfloat16(v.x-__bfloat162float(h0)),
                  l1=__float2bfloat16(v.y-__bfloat162float(h1)),
                  l2=__float2bfloat16(v.z-__bfloat162float(h2)),
                  l3=__float2bfloat16(v.w-__bfloat162float(h3));
    __nv_bfloat162* o0 = (__nv_bfloat162*)(A3 + m*(ll)(3*K) + k4);
    __nv_bfloat162* o1 = (__nv_bfloat162*)(A3 + m*(ll)(3*K) + K + k4);
    __nv_bfloat162* o2 = (__nv_bfloat162*)(A3 + m*(ll)(3*K) + 2*K + k4);
    o0[0] = __nv_bfloat162(h0,h1); o0[1] = __nv_bfloat162(h2,h3);
    o1[0] = __nv_bfloat162(h0,h1); o1[1] = __nv_bfloat162(h2,h3);
    o2[0] = __nv_bfloat162(l0,l1); o2[1] = __nv_bfloat162(l2,l3);
}

__global__ void k_cvtB(const float* __restrict__ B, __nv_bfloat16* __restrict__ B3,
                       int K)
{
    ll idx = (ll)blockIdx.x*256 + threadIdx.x;
    ll n = idx / (K>>2);
    int k4 = (int)(idx % (K>>2)) << 2;
    float4 v = *(const float4*)(B + n*(ll)K + k4);
    __nv_bfloat16 h0=__float2bfloat16(v.x), h1=__float2bfloat16(v.y),
                  h2=__float2bfloat16(v.z), h3=__float2bfloat16(v.w);
    __nv_bfloat16 l0=__float2bfloat16(v.x-__bfloat162float(h0)),
                  l1=__float2bfloat16(v.y-__bfloat162float(h1)),
                  l2=__float2bfloat16(v.z-__bfloat162float(h2)),
                  l3=__float2bfloat16(v.w-__bfloat162float(h3));
    __nv_bfloat162* o0 = (__nv_bfloat162*)(B3 + n*(ll)(3*K) + k4);
    __nv_bfloat162* o1 = (__nv_bfloat162*)(B3 + n*(ll)(3*K) + K + k4);
    __nv_bfloat162* o2 = (__nv_bfloat162*)(B3 + n*(ll)(3*K) + 2*K + k4);
    o0[0] = __nv_bfloat162(h0,h1); o0[1] = __nv_bfloat162(h2,h3);
    o1[0] = __nv_bfloat162(l0,l1); o1[1] = __nv_bfloat162(l2,l3);
    o2[0] = __nv_bfloat162(h0,h1); o2[1] = __nv_bfloat162(h2,h3);
}

// -------------------- bf16 HMMA GEMM v4 (cp.async 3-stage) -------------------
__device__ __forceinline__ u32 s2u(const void* p)
{ return (u32)__cvta_generic_to_shared(p); }

__device__ __forceinline__ void ldsm4(u32* d, u32 a)
{
    asm volatile("ldmatrix.sync.aligned.m8n8.x4.shared.b16 {%0,%1,%2,%3},[%4];"
                 : "=r"(d[0]),"=r"(d[1]),"=r"(d[2]),"=r"(d[3]) : "r"(a));
}
__device__ __forceinline__ void mma16816(float* c, const u32* a, const u32* b)
{
    asm volatile(
        "mma.sync.aligned.m16n8k16.row.col.f32.bf16.bf16.f32 "
        "{%0,%1,%2,%3},{%4,%5,%6,%7},{%8,%9},{%0,%1,%2,%3};"
        : "+f"(c[0]),"+f"(c[1]),"+f"(c[2]),"+f"(c[3])
        : "r"(a[0]),"r"(a[1]),"r"(a[2]),"r"(a[3]),"r"(b[0]),"r"(b[1]));
}
__device__ __forceinline__ void cpa16(u32 dst, const void* src)
{
    asm volatile("cp.async.cg.shared.global [%0],[%1],16;" :: "r"(dst),"l"(src));
}

__global__ __launch_bounds__(256,2) void k_hgemm(
    const __nv_bfloat16* __restrict__ A, const __nv_bfloat16* __restrict__ B,
    const float* __restrict__ bias, float* __restrict__ C,
    int N, int K3, int relu)
{
    extern __shared__ uint4 smX[];
    const u32 sA = s2u(smX);
    const u32 sB = sA + 3*8192;

    const int tid = threadIdx.x;
    const int m0 = blockIdx.y*128, n0 = blockIdx.x*128;
    const int wid = tid>>5, lane = tid&31;
    const int wm = (wid>>2)*64, wn = (wid&3)*32;

    const int c0 = tid*2, c1 = c0+1;
    const int r0=c0>>2, u0=c0&3, r1=c1>>2, u1=c1&3;
    const u32 d0 = (u32)(r0*4 + (u0 ^ ((r0>>1)&3)))*16;
    const u32 d1 = (u32)(r1*4 + (u1 ^ ((r1>>1)&3)))*16;
    const __nv_bfloat16* Ap0 = A + (ll)(m0+r0)*K3 + u0*8;
    const __nv_bfloat16* Ap1 = A + (ll)(m0+r1)*K3 + u1*8;
    const __nv_bfloat16* Bp0 = B + (ll)(n0+r0)*K3 + u0*8;
    const __nv_bfloat16* Bp1 = B + (ll)(n0+r1)*K3 + u1*8;

    float acc[4][4][4];
#pragma unroll
    for (int i=0;i<4;i++)
#pragma unroll
        for (int j=0;j<4;j++)
#pragma unroll
            for (int q=0;q<4;q++) acc[i][j][q]=0.f;

    const int arow = wm + (lane&15);
    const int aup  = lane>>4;
    const int brow = wn + (lane&7) + ((lane>>4)&1)*8;
    const int bup  = (lane>>3)&1;
    const int nk = K3>>5;

#pragma unroll
    for (int st=0; st<2; st++) {
        u32 off = (u32)st*8192;
        int kt = st*32;
        cpa16(sA+off+d0, Ap0+kt); cpa16(sA+off+d1, Ap1+kt);
        cpa16(sB+off+d0, Bp0+kt); cpa16(sB+off+d1, Bp1+kt);
        asm volatile("cp.async.commit_group;");
    }

    for (int it=0; it<nk; it++) {
        asm volatile("cp.async.wait_group 1;");
        __syncthreads();
        if (it+2 < nk) {
            u32 off = (u32)((it+2)%3)*8192;
            int kt = (it+2)*32;
            cpa16(sA+off+d0, Ap0+kt); cpa16(sA+off+d1, Ap1+kt);
            cpa16(sB+off+d0, Bp0+kt); cpa16(sB+off+d1, Bp1+kt);
        }
        asm volatile("cp.async.commit_group;");

        const u32 aB = sA + (u32)(it%3)*8192;
        const u32 bB = sB + (u32)(it%3)*8192;
#pragma unroll
        for (int h=0; h<2; h++) {
            u32 af[4][4], bf[2][4];
#pragma unroll
            for (int i=0;i<4;i++) {
                int rr = arow + i*16;
                int u = h*2 + aup;
                ldsm4(af[i], aB + rr*64 + (u ^ ((rr>>1)&3))*16);
            }
#pragma unroll
            for (int j=0;j<2;j++) {
                int rr = brow + j*16;
                int u = h*2 + bup;
                ldsm4(bf[j], bB + rr*64 + (u ^ ((rr>>1)&3))*16);
            }
#pragma unroll
            for (int i=0;i<4;i++)
#pragma unroll
                for (int j=0;j<2;j++) {
                    mma16816(acc[i][2*j],   af[i], &bf[j][0]);
                    mma16816(acc[i][2*j+1], af[i], &bf[j][2]);
                }
        }
    }

#pragma unroll
    for (int j=0;j<4;j++) {
        int col = n0 + wn + j*8 + (lane&3)*2;
        float b0v = bias[col], b1v = bias[col+1];
#pragma unroll
        for (int i=0;i<4;i++) {
            int mr = m0 + wm + i*16 + (lane>>2);
            float2 v0 = make_float2(acc[i][j][0]+b0v, acc[i][j][1]+b1v);
            float2 v1 = make_float2(acc[i][j][2]+b0v, acc[i][j][3]+b1v);
            if (relu) {
                v0.x=fmaxf(v0.x,0.f); v0.y=fmaxf(v0.y,0.f);
                v1.x=fmaxf(v1.x,0.f); v1.y=fmaxf(v1.y,0.f);
            }
            *(float2*)&C[(ll)mr*N + col]     = v0;
            *(float2*)&C[(ll)(mr+8)*N + col] = v1;
        }
    }
}

// ---------------- LSTM layer v8: st.async DSMEM exchange ---------------------
// Cluster of 8 = one (dir, batch-group). Phase-2 threads push h directly into
// all 8 CTAs' hT[next] via st.async + complete_tx (4 B each); consumer mbarrier
// (count=1, expect_tx 4096 B) IS the step barrier. No L2 traffic for h.
__device__ __forceinline__ ull ff2(ull a, ull b, ull c)
{
    ull d;
    asm("fma.rn.f32x2 %0,%1,%2,%3;" : "=l"(d) : "l"(a),"l"(b),"l"(c));
    return d;
}
__device__ __forceinline__ float acclo(ull a)
{ float l,h; asm("mov.b64 {%0,%1},%2;" : "=f"(l),"=f"(h) : "l"(a)); return l+h; }

#define HT_OFF   32768
#define ZB_OFF   (32768 + 2080)
#define PZ_OFF   (ZB_OFF + 512)
#define MBAR_OFF ((PZ_OFF + 512)*4)            // byte offset, 8B aligned
#define LSTM_SMEM_BYTES (MBAR_OFF + 16)
#define HTX 4096u                              // tx bytes per step per consumer

__global__ __launch_bounds__(256,1) __cluster_dims__(8,1,1)
void k_lstm(
    const float* __restrict__ pref, const float* __restrict__ preb,
    const float* __restrict__ Whhf, const float* __restrict__ Whhb,
    float* __restrict__ out, int nsteps)
{
    extern __shared__ float sm[];
    float* ws = sm;                            // 32768: W swizzled
    float* hT = sm + HT_OFF;                   // [2][4][260]
    float* zb = sm + ZB_OFF;                   // 512
    float* pz = sm + PZ_OFF;                   // 512
    const u32 smu = s2u(sm);

    const int tid = threadIdx.x, blk = blockIdx.x;
    const int dir = blk>>6, bg = (blk>>3)&7, jgrp = blk&7;
    const float* pre = dir ? preb : pref;
    const float* Whh = dir ? Whhb : Whhf;

    // fill W smem (once)
    for (int i = tid; i < 128*64; i += 256) {
        int rr = i>>6, c = i&63;
        int grow = (rr>>5)*256 + jgrp*32 + (rr&31);
        float4 w = *(const float4*)(Whh + (ll)grow*256 + c*4);
        *(float4*)&ws[(rr*64 + (c ^ (rr&15)))*4] = w;
    }
    // zero hT buffer 0 (step 0 reads zeros)
    for (int i = tid; i < 1040; i += 256) hT[i] = 0.f;
    // mbarriers: count=1 (the expect_tx arrive); pre-arm both buffers
    if (tid == 0) {
        asm volatile("mbarrier.init.shared.b64 [%0],%1;" :: "r"(smu+MBAR_OFF),   "r"(1u));
        asm volatile("mbarrier.init.shared.b64 [%0],%1;" :: "r"(smu+MBAR_OFF+8), "r"(1u));
        asm volatile("mbarrier.arrive.expect_tx.shared.b64 _,[%0],%1;"
                     :: "r"(smu+MBAR_OFF),   "r"(HTX) : "memory");
        asm volatile("mbarrier.arrive.expect_tx.shared.b64 _,[%0],%1;"
                     :: "r"(smu+MBAR_OFF+8), "r"(HTX) : "memory");
    }
    __syncthreads();
    asm volatile("barrier.cluster.arrive.aligned;" ::: "memory");
    asm volatile("barrier.cluster.wait.aligned;"   ::: "memory");

    // pz mapping
    const int rr0 = tid & 127;
    const int bl0 = tid >> 7, bl1 = bl0 + 2;
    const ll ga = (ll)((rr0>>5)*256 + jgrp*32 + (rr0&31));
    int tt0 = dir ? (TS-1) : 0;
    float pza = __ldg(pre + ((ll)tt0*32 + bg*4 + bl0)*1024 + ga);
    float pzb = __ldg(pre + ((ll)tt0*32 + bg*4 + bl1)*1024 + ga);

    const int rr  = tid>>1, blp = tid&1;
    const int swk = rr & 15;
    const int jl2 = tid>>2, bl2 = tid&3;
    float creg = 0.f;
    u32 ph0 = 0, ph1 = 0;

    for (int s=0; s<nsteps; s++) {
        const int tt  = dir ? (TS-1-s) : s;
        const int par = s&1;

        if (s >= 1) {                          // wait peers' h (data already local)
            u32 mb = smu + MBAR_OFF + par*8;
            u32 p  = par ? ph1 : ph0;
            u32 done;
            do {
                asm volatile("{.reg .pred p; "
                    "mbarrier.try_wait.parity.acquire.cluster.shared::cta.b64 p,[%1],%2; "
                    "selp.b32 %0,1,0,p;}"
                    : "=r"(done) : "r"(mb), "r"(p));
            } while (!done);
            if (par) ph1 ^= 1; else ph0 ^= 1;
            // re-arm this buffer for step s+2 (safe: producers for that phase
            // are gated through OUR phase-2 tx on the other buffer)
            if (tid == 0 && s+2 < nsteps)
                asm volatile("mbarrier.arrive.expect_tx.shared.b64 _,[%0],%1;"
                             :: "r"(mb), "r"(HTX) : "memory");
        }

        pz[rr0*4 + bl0] = pza;
        pz[rr0*4 + bl1] = pzb;
        __syncthreads();

        if (s+1 < nsteps) {                    // prefetch next pz
            int tn = dir ? (TS-2-s) : (s+1);
            pza = __ldg(pre + ((ll)tn*32 + bg*4 + bl0)*1024 + ga);
            pzb = __ldg(pre + ((ll)tn*32 + bg*4 + bl1)*1024 + ga);
        }

        // phase 1: full-K dots from hT[par]
        const float* hP = &hT[par*1040];
        ull a0=0ull, a1=0ull, a2=0ull, a3=0ull;
#pragma unroll 8
        for (int c=0; c<64; c++) {
            ulonglong2 wv = *(const ulonglong2*)&ws[(rr*64 + (c ^ swk))*4];
            ulonglong2 ha = *(const ulonglong2*)&hP[blp*260 + c*4];
            ulonglong2 hb = *(const ulonglong2*)&hP[(blp+2)*260 + c*4];
            a0 = ff2(wv.x, ha.x, a0); a1 = ff2(wv.y, ha.y, a1);
            a2 = ff2(wv.x, hb.x, a2); a3 = ff2(wv.y, hb.y, a3);
        }
        zb[rr*4 + blp]     = acclo(a0) + acclo(a1);
        zb[rr*4 + blp + 2] = acclo(a2) + acclo(a3);
        __syncthreads();

        // phase 2: gates + state; push h to all 8 cluster CTAs via st.async
        if (tid < 128) {
            float zi = zb[(0*32+jl2)*4+bl2] + pz[(0*32+jl2)*4+bl2];
            float zf = zb[(1*32+jl2)*4+bl2] + pz[(1*32+jl2)*4+bl2];
            float zg = zb[(2*32+jl2)*4+bl2] + pz[(2*32+jl2)*4+bl2];
            float zo = zb[(3*32+jl2)*4+bl2] + pz[(3*32+jl2)*4+bl2];
            float ig = 1.f/(1.f+__expf(-zi));
            float fg = 1.f/(1.f+__expf(-zf));
            float gv = tanhf(zg);
            float og = 1.f/(1.f+__expf(-zo));
            float cn = fg*creg + ig*gv;
            creg = cn;
            float hval = og*tanhf(cn);
            if (s+1 < nsteps) {
                const int b1p = par^1;
                u32 loc = smu + (u32)(HT_OFF + b1p*1040 + bl2*260 + jgrp*32 + jl2)*4;
                u32 mbl = smu + MBAR_OFF + b1p*8;
                u32 hbits = __float_as_uint(hval);
#pragma unroll
                for (int rk=0; rk<8; rk++) {
                    u32 rem, mrem;
                    asm("mapa.shared::cluster.u32 %0,%1,%2;" : "=r"(rem)  : "r"(loc), "r"(rk));
                    asm("mapa.shared::cluster.u32 %0,%1,%2;" : "=r"(mrem) : "r"(mbl), "r"(rk));
                    asm volatile(
                        "st.async.weak.shared::cluster.mbarrier::complete_tx::bytes.b32 [%0],%1,[%2];"
                        :: "r"(rem), "r"(hbits), "r"(mrem) : "memory");
                }
            }
            out[((ll)tt*32 + bg*4 + bl2)*512 + dir*256 + jgrp*32 + jl2] = hval;
        }
        __syncthreads();                       // protect zb/pz reuse next step
    }

    // no CTA may exit while peers' st.async into it could be in flight
    asm volatile("barrier.cluster.arrive.aligned;" ::: "memory");
    asm volatile("barrier.cluster.wait.aligned;"   ::: "memory");
}

// ------------------------------ LayerNorm ------------------------------------
__global__ void k_ln(const float* __restrict__ gamma, const float* __restrict__ beta)
{
    __shared__ float s1s[16], s2s[16], mv[2];
    const int row = blockIdx.x, tid = threadIdx.x;
    const ll base = (ll)row*512;
    float z = g_h1[base+tid] + g_res[base+tid];
    float s1 = z, s2 = z*z;
#pragma unroll
    for (int o=16;o;o>>=1) {
        s1 += __shfl_xor_sync(~0u,s1,o);
        s2 += __shfl_xor_sync(~0u,s2,o);
    }
    if ((tid&31)==0) { s1s[tid>>5]=s1; s2s[tid>>5]=s2; }
    __syncthreads();
    if (tid < 32) {
        float a = tid<16 ? s1s[tid] : 0.f;
        float b = tid<16 ? s2s[tid] : 0.f;
#pragma unroll
        for (int o=8;o;o>>=1) {
            a += __shfl_xor_sync(~0u,a,o);
            b += __shfl_xor_sync(~0u,b,o);
        }
        if (tid==0) {
            float mu = a*(1.f/512.f);
            mv[0] = mu;
            mv[1] = rsqrtf(b*(1.f/512.f) - mu*mu + 1e-5f);
        }
    }
    __syncthreads();
    g_pref[base+tid] = (z - mv[0])*mv[1]*gamma[tid] + beta[tid];
}

// ------------------------------ final logits ---------------------------------
__global__ void k_c2(const float* __restrict__ Wc2, const float* __restrict__ bc2,
                     float* __restrict__ out)
{
    int w = (blockIdx.x*256 + threadIdx.x)>>5;
    int lane = threadIdx.x & 31;
    if (w >= NR) return;
    float4 h4 = ((const float4*)&g_hid[(ll)w*128])[lane];
    float4 w4 = ((const float4*)Wc2)[lane];
    float s = h4.x*w4.x + h4.y*w4.y + h4.z*w4.z + h4.w*w4.w;
#pragma unroll
    for (int o=16;o;o>>=1) s += __shfl_xor_sync(~0u,s,o);
    if (lane==0) {
        int t = w>>5, b = w&31;
        out[(ll)b*TS + t] = s + bc2[0];
    }
}

// ------------------------------ launcher -------------------------------------
extern "C" void kernel_launch(void* const* d_in, const int* in_sizes, int n_in,
                              void* d_out, int out_size)
{
    const float* x     = (const float*)d_in[0];
    const float* Wih0f = (const float*)d_in[1];
    const float* Whh0f = (const float*)d_in[2];
    const float* b0f   = (const float*)d_in[3];
    const float* Wih0b = (const float*)d_in[4];
    const float* Whh0b = (const float*)d_in[5];
    const float* b0b   = (const float*)d_in[6];
    const float* Wih1f = (const float*)d_in[7];
    const float* Whh1f = (const float*)d_in[8];
    const float* b1f   = (const float*)d_in[9];
    const float* Wih1b = (const float*)d_in[10];
    const float* Whh1b = (const float*)d_in[11];
    const float* b1b   = (const float*)d_in[12];
    const float* Wres  = (const float*)d_in[13];
    const float* bres  = (const float*)d_in[14];
    const float* gamma = (const float*)d_in[15];
    const float* beta  = (const float*)d_in[16];
    const float* Wc1   = (const float*)d_in[17];
    const float* bc1   = (const float*)d_in[18];
    const float* Wc2   = (const float*)d_in[19];
    const float* bc2   = (const float*)d_in[20];
    float* out = (float*)d_out;

    void *pf,*pb,*rs,*h0p,*h1p,*hd,*a3,*b3;
    cudaGetSymbolAddress(&pf,  g_pref);
    cudaGetSymbolAddress(&pb,  g_preb);
    cudaGetSymbolAddress(&rs,  g_res);
    cudaGetSymbolAddress(&h0p, g_h0);
    cudaGetSymbolAddress(&h1p, g_h1);
    cudaGetSymbolAddress(&hd,  g_hid);
    cudaGetSymbolAddress(&a3,  g_a3);
    cudaGetSymbolAddress(&b3,  g_b3);
    __nv_bfloat16* A3 = (__nv_bfloat16*)a3;
    __nv_bfloat16* B3r = (__nv_bfloat16*)b3;
    __nv_bfloat16* B3f = B3r + (ll)1024*3072;
    __nv_bfloat16* B3b = B3f + (ll)1024*3072;

    const int gemm_smem = 49152;
    cudaFuncSetAttribute(k_lstm,  cudaFuncAttributeMaxDynamicSharedMemorySize, LSTM_SMEM_BYTES);
    cudaFuncSetAttribute(k_hgemm, cudaFuncAttributeMaxDynamicSharedMemorySize, gemm_smem);

    // launches 1-3, then #4 = big hgemm (ncu lands here)
    k_cvtA<<<65536,256>>>(x, A3, 1024, 1);
    k_cvtB<<<1024,256>>>(Wih0f, B3f, 1024);
    k_cvtB<<<1024,256>>>(Wih0b, B3b, 1024);
    k_hgemm<<<dim3(8,512),256,gemm_smem>>>(A3, B3f, b0f, (float*)pf, 1024, 3072, 0);
    k_hgemm<<<dim3(8,512),256,gemm_smem>>>(A3, B3b, b0b, (float*)pb, 1024, 3072, 0);
    k_cvtB<<<512,256>>>(Wres,  B3r, 1024);
    k_hgemm<<<dim3(4,512),256,gemm_smem>>>(A3, B3r, bres, (float*)rs, 512, 3072, 0);

    // layer 0 recurrence
    k_lstm<<<128,256,LSTM_SMEM_BYTES>>>((const float*)pf,(const float*)pb,
                                        Whh0f, Whh0b, (float*)h0p, TS);

    // layer 1 projections
    k_cvtA<<<32768,256>>>((const float*)h0p, A3, 512, 0);
    k_cvtB<<<512,256>>>(Wih1f, B3f, 512);
    k_cvtB<<<512,256>>>(Wih1b, B3b, 512);
    k_hgemm<<<dim3(8,512),256,gemm_smem>>>(A3, B3f, b1f, (float*)pf, 1024, 1536, 0);
    k_hgemm<<<dim3(8,512),256,gemm_smem>>>(A3, B3b, b1b, (float*)pb, 1024, 1536, 0);

    // layer 1 recurrence
    k_lstm<<<128,256,LSTM_SMEM_BYTES>>>((const float*)pf,(const float*)pb,
                                        Whh1f, Whh1b, (float*)h1p, TS);

    // LayerNorm -> g_pref (fp32)
    k_ln<<<NR,512>>>(gamma, beta);

    // classifier
    k_cvtA<<<32768,256>>>((const float*)pf, A3, 512, 0);
    k_cvtB<<<64,256>>>(Wc1, B3f, 512);
    k_hgemm<<<dim3(1,512),256,gemm_smem>>>(A3, B3f, bc1, (float*)hd, 128, 1536, 1);
    k_c2<<<8192,256>>>(Wc2, bc2, out);
}

// round 17
// speedup vs baseline: 1.2889x; 1.2889x over previous
#include <cuda_runtime.h>
#include <cuda_bf16.h>
#include <math.h>

#define TS 2048
#define NR 65536
typedef long long ll;
typedef unsigned int u32;
typedef unsigned long long ull;

// ------------------------- scratch (no allocations) -------------------------
__device__ float g_pref[(ll)NR*1024];
__device__ float g_preb[(ll)NR*1024];
__device__ float g_res [(ll)NR*512];
__device__ float g_h1  [(ll)NR*512];
__device__ float g_hid [(ll)NR*128];
__device__ float g_hx  [32768];                    // [dir][bg][par][256 k][4 bl]
__device__ unsigned g_cnt[512];                    // 16 barriers, 128B apart
__device__ __nv_bfloat16 g_a3[(ll)NR*3072];        // split-bf16 A
__device__ __nv_bfloat16 g_b3[3][(ll)1024*3072];   // split-bf16 weights, 3 slots

// ------------------------------ init ----------------------------------------
__global__ void k_init()
{
    int i = blockIdx.x*256 + threadIdx.x;
    if (i < 32768) g_hx[i]  = 0.f;
    if (i < 512)   g_cnt[i] = 0u;
}

// ---------------------- fp32 -> split bf16 conversions -----------------------
__global__ void k_cvtA(const float* __restrict__ A, __nv_bfloat16* __restrict__ A3,
                       int K, int flags)
{
    ll idx = (ll)blockIdx.x*256 + threadIdx.x;
    ll m = idx / (K>>2);
    int k4 = (int)(idx % (K>>2)) << 2;
    const float* src = (flags&1) ? A + ((m&31)*(ll)TS + (m>>5))*K + k4
                                 : A + m*(ll)K + k4;
    float4 v = *(const float4*)src;
    if (flags&1) {
        v.x=(v.x==v.x)?v.x:0.f; v.y=(v.y==v.y)?v.y:0.f;
        v.z=(v.z==v.z)?v.z:0.f; v.w=(v.w==v.w)?v.w:0.f;
    }
    __nv_bfloat16 h0=__float2bfloat16(v.x), h1=__float2bfloat16(v.y),
                  h2=__float2bfloat16(v.z), h3=__float2bfloat16(v.w);
    __nv_bfloat16 l0=__float2bfloat16(v.x-__bfloat162float(h0)),
                  l1=__float2bfloat16(v.y-__bfloat162float(h1)),
                  l2=__float2bfloat16(v.z-__bfloat162float(h2)),
                  l3=__float2bfloat16(v.w-__bfloat162float(h3));
    __nv_bfloat162* o0 = (__nv_bfloat162*)(A3 + m*(ll)(3*K) + k4);
    __nv_bfloat162* o1 = (__nv_bfloat162*)(A3 + m*(ll)(3*K) + K + k4);
    __nv_bfloat162* o2 = (__nv_bfloat162*)(A3 + m*(ll)(3*K) + 2*K + k4);
    o0[0] = __nv_bfloat162(h0,h1); o0[1] = __nv_bfloat162(h2,h3);
    o1[0] = __nv_bfloat162(h0,h1); o1[1] = __nv_bfloat162(h2,h3);
    o2[0] = __nv_bfloat162(l0,l1); o2[1] = __nv_bfloat162(l2,l3);
}

__global__ void k_cvtB(const float* __restrict__ B, __nv_bfloat16* __restrict__ B3,
                       int K)
{
    ll idx = (ll)blockIdx.x*256 + threadIdx.x;
    ll n = idx / (K>>2);
    int k4 = (int)(idx % (K>>2)) << 2;
    float4 v = *(const float4*)(B + n*(ll)K + k4);
    __nv_bfloat16 h0=__float2bfloat16(v.x), h1=__float2bfloat16(v.y),
                  h2=__float2bfloat16(v.z), h3=__float2bfloat16(v.w);
    __nv_bfloat16 l0=__float2bfloat16(v.x-__bfloat162float(h0)),
                  l1=__float2bfloat16(v.y-__bfloat162float(h1)),
                  l2=__float2bfloat16(v.z-__bfloat162float(h2)),
                  l3=__float2bfloat16(v.w-__bfloat162float(h3));
    __nv_bfloat162* o0 = (__nv_bfloat162*)(B3 + n*(ll)(3*K) + k4);
    __nv_bfloat162* o1 = (__nv_bfloat162*)(B3 + n*(ll)(3*K) + K + k4);
    __nv_bfloat162* o2 = (__nv_bfloat162*)(B3 + n*(ll)(3*K) + 2*K + k4);
    o0[0] = __nv_bfloat162(h0,h1); o0[1] = __nv_bfloat162(h2,h3);
    o1[0] = __nv_bfloat162(l0,l1); o1[1] = __nv_bfloat162(l2,l3);
    o2[0] = __nv_bfloat162(h0,h1); o2[1] = __nv_bfloat162(h2,h3);
}

// -------------------- bf16 HMMA GEMM v4 (cp.async 3-stage) -------------------
__device__ __forceinline__ u32 s2u(const void* p)
{ return (u32)__cvta_generic_to_shared(p); }

__device__ __forceinline__ void ldsm4(u32* d, u32 a)
{
    asm volatile("ldmatrix.sync.aligned.m8n8.x4.shared.b16 {%0,%1,%2,%3},[%4];"
                 : "=r"(d[0]),"=r"(d[1]),"=r"(d[2]),"=r"(d[3]) : "r"(a));
}
__device__ __forceinline__ void mma16816(float* c, const u32* a, const u32* b)
{
    asm volatile(
        "mma.sync.aligned.m16n8k16.row.col.f32.bf16.bf16.f32 "
        "{%0,%1,%2,%3},{%4,%5,%6,%7},{%8,%9},{%0,%1,%2,%3};"
        : "+f"(c[0]),"+f"(c[1]),"+f"(c[2]),"+f"(c[3])
        : "r"(a[0]),"r"(a[1]),"r"(a[2]),"r"(a[3]),"r"(b[0]),"r"(b[1]));
}
__device__ __forceinline__ void cpa16(u32 dst, const void* src)
{
    asm volatile("cp.async.cg.shared.global [%0],[%1],16;" :: "r"(dst),"l"(src));
}

__global__ __launch_bounds__(256,2) void k_hgemm(
    const __nv_bfloat16* __restrict__ A, const __nv_bfloat16* __restrict__ B,
    const float* __restrict__ bias, float* __restrict__ C,
    int N, int K3, int relu)
{
    extern __shared__ uint4 smX[];
    const u32 sA = s2u(smX);
    const u32 sB = sA + 3*8192;

    const int tid = threadIdx.x;
    const int m0 = blockIdx.y*128, n0 = blockIdx.x*128;
    const int wid = tid>>5, lane = tid&31;
    const int wm = (wid>>2)*64, wn = (wid&3)*32;

    const int c0 = tid*2, c1 = c0+1;
    const int r0=c0>>2, u0=c0&3, r1=c1>>2, u1=c1&3;
    const u32 d0 = (u32)(r0*4 + (u0 ^ ((r0>>1)&3)))*16;
    const u32 d1 = (u32)(r1*4 + (u1 ^ ((r1>>1)&3)))*16;
    const __nv_bfloat16* Ap0 = A + (ll)(m0+r0)*K3 + u0*8;
    const __nv_bfloat16* Ap1 = A + (ll)(m0+r1)*K3 + u1*8;
    const __nv_bfloat16* Bp0 = B + (ll)(n0+r0)*K3 + u0*8;
    const __nv_bfloat16* Bp1 = B + (ll)(n0+r1)*K3 + u1*8;

    float acc[4][4][4];
#pragma unroll
    for (int i=0;i<4;i++)
#pragma unroll
        for (int j=0;j<4;j++)
#pragma unroll
            for (int q=0;q<4;q++) acc[i][j][q]=0.f;

    const int arow = wm + (lane&15);
    const int aup  = lane>>4;
    const int brow = wn + (lane&7) + ((lane>>4)&1)*8;
    const int bup  = (lane>>3)&1;
    const int nk = K3>>5;

#pragma unroll
    for (int st=0; st<2; st++) {
        u32 off = (u32)st*8192;
        int kt = st*32;
        cpa16(sA+off+d0, Ap0+kt); cpa16(sA+off+d1, Ap1+kt);
        cpa16(sB+off+d0, Bp0+kt); cpa16(sB+off+d1, Bp1+kt);
        asm volatile("cp.async.commit_group;");
    }

    for (int it=0; it<nk; it++) {
        asm volatile("cp.async.wait_group 1;");
        __syncthreads();
        if (it+2 < nk) {
            u32 off = (u32)((it+2)%3)*8192;
            int kt = (it+2)*32;
            cpa16(sA+off+d0, Ap0+kt); cpa16(sA+off+d1, Ap1+kt);
            cpa16(sB+off+d0, Bp0+kt); cpa16(sB+off+d1, Bp1+kt);
        }
        asm volatile("cp.async.commit_group;");

        const u32 aB = sA + (u32)(it%3)*8192;
        const u32 bB = sB + (u32)(it%3)*8192;
#pragma unroll
        for (int h=0; h<2; h++) {
            u32 af[4][4], bf[2][4];
#pragma unroll
            for (int i=0;i<4;i++) {
                int rr = arow + i*16;
                int u = h*2 + aup;
                ldsm4(af[i], aB + rr*64 + (u ^ ((rr>>1)&3))*16);
            }
#pragma unroll
            for (int j=0;j<2;j++) {
                int rr = brow + j*16;
                int u = h*2 + bup;
                ldsm4(bf[j], bB + rr*64 + (u ^ ((rr>>1)&3))*16);
            }
#pragma unroll
            for (int i=0;i<4;i++)
#pragma unroll
                for (int j=0;j<2;j++) {
                    mma16816(acc[i][2*j],   af[i], &bf[j][0]);
                    mma16816(acc[i][2*j+1], af[i], &bf[j][2]);
                }
        }
    }

#pragma unroll
    for (int j=0;j<4;j++) {
        int col = n0 + wn + j*8 + (lane&3)*2;
        float b0v = bias[col], b1v = bias[col+1];
#pragma unroll
        for (int i=0;i<4;i++) {
            int mr = m0 + wm + i*16 + (lane>>2);
            float2 v0 = make_float2(acc[i][j][0]+b0v, acc[i][j][1]+b1v);
            float2 v1 = make_float2(acc[i][j][2]+b0v, acc[i][j][3]+b1v);
            if (relu) {
                v0.x=fmaxf(v0.x,0.f); v0.y=fmaxf(v0.y,0.f);
                v1.x=fmaxf(v1.x,0.f); v1.y=fmaxf(v1.y,0.f);
            }
            *(float2*)&C[(ll)mr*N + col]     = v0;
            *(float2*)&C[(ll)(mr+8)*N + col] = v1;
        }
    }
}

// ------------------- LSTM layer (R13/R15 best + fused bf16 out) --------------
__device__ __forceinline__ ull ff2(ull a, ull b, ull c)
{
    ull d;
    asm("fma.rn.f32x2 %0,%1,%2,%3;" : "=l"(d) : "l"(a),"l"(b),"l"(c));
    return d;
}
__device__ __forceinline__ float acclo(ull a)
{ float l,h; asm("mov.b64 {%0,%1},%2;" : "=f"(l),"=f"(h) : "l"(a)); return l+h; }

#define LSTM_SMEM_FLOATS (32768 + 1040 + 512 + 512)

// outmode 0: out[...] = h (fp32). outmode 1: split-bf16 into a3out rows of 1536
// ([Hh | Hh | Hl] layout matching k_cvtA with K=512).
__global__ __launch_bounds__(256,1) void k_lstm(
    const float* __restrict__ pref, const float* __restrict__ preb,
    const float* __restrict__ Whhf, const float* __restrict__ Whhb,
    float* __restrict__ out, __nv_bfloat16* __restrict__ a3out,
    int outmode, int nsteps)
{
    extern __shared__ float sm[];
    float* ws  = sm;                          // 32768: W [128 rows][64 chunks] swizzled
    float* hTb = sm + 32768;                  // 1040:  h [4 bl][260]
    float* zb  = sm + 32768 + 1040;           // 512:   z [128 rows][4 bl]
    float* pz  = sm + 32768 + 1040 + 512;     // 512:   pre [128 rows][4 bl]

    const int tid = threadIdx.x, blk = blockIdx.x;
    const int dir = blk>>6, bg = (blk>>3)&7, jgrp = blk&7;
    const float* pre = dir ? preb : pref;
    const float* Whh = dir ? Whhb : Whhf;
    unsigned* cnt = &g_cnt[(dir*8+bg)*32];
    float* hx = g_hx + (dir*8+bg)*2048;       // [par][256][4]

    // fill W smem (once)
    for (int i = tid; i < 128*64; i += 256) {
        int rr = i>>6, c = i&63;
        int grow = (rr>>5)*256 + jgrp*32 + (rr&31);
        float4 w = *(const float4*)(Whh + (ll)grow*256 + c*4);
        *(float4*)&ws[(rr*64 + (c ^ (rr&15)))*4] = w;
    }

    const int rr0 = tid & 127;
    const int bl0 = tid >> 7, bl1 = bl0 + 2;
    const ll ga = (ll)((rr0>>5)*256 + jgrp*32 + (rr0&31));
    int tt0 = dir ? (TS-1) : 0;
    float pza = __ldg(pre + ((ll)tt0*32 + bg*4 + bl0)*1024 + ga);
    float pzb = __ldg(pre + ((ll)tt0*32 + bg*4 + bl1)*1024 + ga);

    const int rr  = tid>>1, blp = tid&1;
    const int swk = rr & 15;
    const int jl2 = tid>>2, bl2 = tid&3;
    float creg = 0.f;

    for (int s=0; s<nsteps; s++) {
        const int tt  = dir ? (TS-1-s) : s;
        const int par = s&1;

        // fill hTb (transpose [k][4bl] -> [bl][k]) + pz
        {
            float4 h4 = __ldcg((const float4*)(hx + par*1024) + tid);
            hTb[0*260 + tid] = h4.x; hTb[1*260 + tid] = h4.y;
            hTb[2*260 + tid] = h4.z; hTb[3*260 + tid] = h4.w;
        }
        pz[rr0*4 + bl0] = pza;
        pz[rr0*4 + bl1] = pzb;
        __syncthreads();

        // prefetch next step's pz
        if (s+1 < nsteps) {
            int tn = dir ? (TS-2-s) : (s+1);
            pza = __ldg(pre + ((ll)tn*32 + bg*4 + bl0)*1024 + ga);
            pzb = __ldg(pre + ((ll)tn*32 + bg*4 + bl1)*1024 + ga);
        }

        // phase 1: full-K dots, k packed in f32x2
        ull a0=0ull, a1=0ull, a2=0ull, a3=0ull;
#pragma unroll 8
        for (int c=0; c<64; c++) {
            ulonglong2 wv = *(const ulonglong2*)&ws[(rr*64 + (c ^ swk))*4];
            ulonglong2 ha = *(const ulonglong2*)&hTb[blp*260 + c*4];
            ulonglong2 hb = *(const ulonglong2*)&hTb[(blp+2)*260 + c*4];
            a0 = ff2(wv.x, ha.x, a0); a1 = ff2(wv.y, ha.y, a1);
            a2 = ff2(wv.x, hb.x, a2); a3 = ff2(wv.y, hb.y, a3);
        }
        zb[rr*4 + blp]     = acclo(a0) + acclo(a1);
        zb[rr*4 + blp + 2] = acclo(a2) + acclo(a3);
        __syncthreads();

        // phase 2: gates + state update (tid<128: one (j,b) each)
        if (tid < 128) {
            float zi = zb[(0*32+jl2)*4+bl2] + pz[(0*32+jl2)*4+bl2];
            float zf = zb[(1*32+jl2)*4+bl2] + pz[(1*32+jl2)*4+bl2];
            float zg = zb[(2*32+jl2)*4+bl2] + pz[(2*32+jl2)*4+bl2];
            float zo = zb[(3*32+jl2)*4+bl2] + pz[(3*32+jl2)*4+bl2];
            float ig = 1.f/(1.f+__expf(-zi));
            float fg = 1.f/(1.f+__expf(-zf));
            float gv = tanhf(zg);
            float og = 1.f/(1.f+__expf(-zo));
            float cn = fg*creg + ig*gv;
            creg = cn;
            float hval = og*tanhf(cn);
            hx[(par^1)*1024 + (jgrp*32+jl2)*4 + bl2] = hval;
            ll mrow = (ll)tt*32 + bg*4 + bl2;
            int col  = dir*256 + jgrp*32 + jl2;
            if (outmode == 0) {
                out[mrow*512 + col] = hval;
            } else {
                __nv_bfloat16 hh = __float2bfloat16(hval);
                __nv_bfloat16 hl = __float2bfloat16(hval - __bfloat162float(hh));
                __nv_bfloat16* rp2 = a3out + mrow*1536;
                rp2[col] = hh; rp2[512 + col] = hh; rp2[1024 + col] = hl;
            }
        }
        __syncthreads();
        if (tid == 0)
            asm volatile("red.release.gpu.global.add.u32 [%0],%1;"
                         :: "l"(cnt), "r"(1u) : "memory");

        if (s+1 < nsteps) {       // all-thread acquire poll
            unsigned target = 8u*(unsigned)(s+1), v;
            do {
                asm volatile("ld.acquire.gpu.global.u32 %0,[%1];"
                             : "=r"(v) : "l"(cnt));
            } while (v < target);
        }
    }
}

// --------------- LayerNorm (fused split-bf16 output into A3) -----------------
__global__ void k_ln(const float* __restrict__ gamma, const float* __restrict__ beta,
                     __nv_bfloat16* __restrict__ A3)
{
    __shared__ float s1s[16], s2s[16], mv[2];
    const int row = blockIdx.x, tid = threadIdx.x;   // 512 threads
    const ll base = (ll)row*512;
    float z = g_h1[base+tid] + g_res[base+tid];
    float s1 = z, s2 = z*z;
#pragma unroll
    for (int o=16;o;o>>=1) {
        s1 += __shfl_xor_sync(~0u,s1,o);
        s2 += __shfl_xor_sync(~0u,s2,o);
    }
    if ((tid&31)==0) { s1s[tid>>5]=s1; s2s[tid>>5]=s2; }
    __syncthreads();
    if (tid < 32) {
        float a = tid<16 ? s1s[tid] : 0.f;
        float b = tid<16 ? s2s[tid] : 0.f;
#pragma unroll
        for (int o=8;o;o>>=1) {
            a += __shfl_xor_sync(~0u,a,o);
            b += __shfl_xor_sync(~0u,b,o);
        }
        if (tid==0) {
            float mu = a*(1.f/512.f);
            mv[0] = mu;
            mv[1] = rsqrtf(b*(1.f/512.f) - mu*mu + 1e-5f);
        }
    }
    __syncthreads();
    float val = (z - mv[0])*mv[1]*gamma[tid] + beta[tid];
    __nv_bfloat16 hh = __float2bfloat16(val);
    __nv_bfloat16 hl = __float2bfloat16(val - __bfloat162float(hh));
    __nv_bfloat16* rp = A3 + (ll)row*1536;
    rp[tid] = hh; rp[512 + tid] = hh; rp[1024 + tid] = hl;
}

// ------------------------------ final logits ---------------------------------
__global__ void k_c2(const float* __restrict__ Wc2, const float* __restrict__ bc2,
                     float* __restrict__ out)
{
    int w = (blockIdx.x*256 + threadIdx.x)>>5;
    int lane = threadIdx.x & 31;
    if (w >= NR) return;
    float4 h4 = ((const float4*)&g_hid[(ll)w*128])[lane];
    float4 w4 = ((const float4*)Wc2)[lane];
    float s = h4.x*w4.x + h4.y*w4.y + h4.z*w4.z + h4.w*w4.w;
#pragma unroll
    for (int o=16;o;o>>=1) s += __shfl_xor_sync(~0u,s,o);
    if (lane==0) {
        int t = w>>5, b = w&31;
        out[(ll)b*TS + t] = s + bc2[0];
    }
}

// ------------------------------ launcher -------------------------------------
extern "C" void kernel_launch(void* const* d_in, const int* in_sizes, int n_in,
                              void* d_out, int out_size)
{
    const float* x     = (const float*)d_in[0];
    const float* Wih0f = (const float*)d_in[1];
    const float* Whh0f = (const float*)d_in[2];
    const float* b0f   = (const float*)d_in[3];
    const float* Wih0b = (const float*)d_in[4];
    const float* Whh0b = (const float*)d_in[5];
    const float* b0b   = (const float*)d_in[6];
    const float* Wih1f = (const float*)d_in[7];
    const float* Whh1f = (const float*)d_in[8];
    const float* b1f   = (const float*)d_in[9];
    const float* Wih1b = (const float*)d_in[10];
    const float* Whh1b = (const float*)d_in[11];
    const float* b1b   = (const float*)d_in[12];
    const float* Wres  = (const float*)d_in[13];
    const float* bres  = (const float*)d_in[14];
    const float* gamma = (const float*)d_in[15];
    const float* beta  = (const float*)d_in[16];
    const float* Wc1   = (const float*)d_in[17];
    const float* bc1   = (const float*)d_in[18];
    const float* Wc2   = (const float*)d_in[19];
    const float* bc2   = (const float*)d_in[20];
    float* out = (float*)d_out;

    void *pf,*pb,*rs,*h1p,*hd,*a3,*b3;
    cudaGetSymbolAddress(&pf,  g_pref);
    cudaGetSymbolAddress(&pb,  g_preb);
    cudaGetSymbolAddress(&rs,  g_res);
    cudaGetSymbolAddress(&h1p, g_h1);
    cudaGetSymbolAddress(&hd,  g_hid);
    cudaGetSymbolAddress(&a3,  g_a3);
    cudaGetSymbolAddress(&b3,  g_b3);
    __nv_bfloat16* A3 = (__nv_bfloat16*)a3;
    __nv_bfloat16* B3r = (__nv_bfloat16*)b3;
    __nv_bfloat16* B3f = B3r + (ll)1024*3072;
    __nv_bfloat16* B3b = B3f + (ll)1024*3072;

    const int lstm_smem = LSTM_SMEM_FLOATS*4;     // 139,328 B
    const int gemm_smem = 49152;
    cudaFuncSetAttribute(k_lstm,  cudaFuncAttributeMaxDynamicSharedMemorySize, lstm_smem);
    cudaFuncSetAttribute(k_hgemm, cudaFuncAttributeMaxDynamicSharedMemorySize, gemm_smem);

    // launches 1-3, then #4 = big hgemm (ncu lands here)
    k_cvtA<<<65536,256>>>(x, A3, 1024, 1);
    k_cvtB<<<1024,256>>>(Wih0f, B3f, 1024);
    k_cvtB<<<1024,256>>>(Wih0b, B3b, 1024);
    k_hgemm<<<dim3(8,512),256,gemm_smem>>>(A3, B3f, b0f, (float*)pf, 1024, 3072, 0);
    k_hgemm<<<dim3(8,512),256,gemm_smem>>>(A3, B3b, b0b, (float*)pb, 1024, 3072, 0);
    k_cvtB<<<512,256>>>(Wres,  B3r, 1024);
    k_hgemm<<<dim3(4,512),256,gemm_smem>>>(A3, B3r, bres, (float*)rs, 512, 3072, 0);

    // layer 0 recurrence — writes split-bf16 h0 directly into A3 (outmode 1)
    k_init<<<128,256>>>();
    k_lstm<<<128,256,lstm_smem>>>((const float*)pf,(const float*)pb,
                                  Whh0f, Whh0b, (float*)h1p, A3, 1, TS);

    // layer 1 projections (A3 already holds split-bf16 h0)
    k_cvtB<<<512,256>>>(Wih1f, B3f, 512);
    k_cvtB<<<512,256>>>(Wih1b, B3b, 512);
    k_hgemm<<<dim3(8,512),256,gemm_smem>>>(A3, B3f, b1f, (float*)pf, 1024, 1536, 0);
    k_hgemm<<<dim3(8,512),256,gemm_smem>>>(A3, B3b, b1b, (float*)pb, 1024, 1536, 0);

    // layer 1 recurrence — fp32 out (LN needs it)
    k_init<<<128,256>>>();
    k_lstm<<<128,256,lstm_smem>>>((const float*)pf,(const float*)pb,
                                  Whh1f, Whh1b, (float*)h1p, A3, 0, TS);

    // LayerNorm(h1 + res) -> split-bf16 directly into A3
    k_ln<<<NR,512>>>(gamma, beta, A3);

    // classifier
    k_cvtB<<<64,256>>>(Wc1, B3f, 512);
    k_hgemm<<<dim3(1,512),256,gemm_smem>>>(A3, B3f, bc1, (float*)hd, 128, 1536, 1);
    k_c2<<<8192,256>>>(Wc2, bc2, out);
}